// round 1
// baseline (speedup 1.0000x reference)
#include <cuda_runtime.h>

#define T_LEVELS    21
#define IN_DIM      4096
#define OUT_DIM     32
#define PREFIX_BITS 17
#define SUFFIX_BITS 3          // PREFIX_BITS + SUFFIX_BITS = 20; bit 20 is j0
#define N_PRE       (4 + OUT_DIM)

// Scratch for precomputed dot products (allowed: __device__ global, no alloc).
__device__ float g_pre[N_PRE];

// ---------------------------------------------------------------------------
// Kernel 1: 36 dot products of x (4096) with rows of in_left/in_right/out_layer0
//   g_pre[0..1] = left0  (incl. bias)
//   g_pre[2..3] = right0 (incl. bias)
//   g_pre[4..35]= x@W0.T + out_bias   (the base accumulator A0)
// ---------------------------------------------------------------------------
__global__ void precompute_kernel(const float* __restrict__ x,
                                  const float* __restrict__ wl,
                                  const float* __restrict__ wr,
                                  const float* __restrict__ bl,
                                  const float* __restrict__ br,
                                  const float* __restrict__ w0,
                                  const float* __restrict__ ob)
{
    int r = blockIdx.x;            // 0..35
    const float* src;
    if (r < 2)       src = wl + r * IN_DIM;
    else if (r < 4)  src = wr + (r - 2) * IN_DIM;
    else             src = w0 + (r - 4) * IN_DIM;

    float s = 0.0f;
    for (int i = threadIdx.x; i < IN_DIM; i += blockDim.x)
        s = fmaf(x[i], src[i], s);

    __shared__ float red[8];
    #pragma unroll
    for (int o = 16; o > 0; o >>= 1) s += __shfl_down_sync(0xffffffffu, s, o);
    if ((threadIdx.x & 31) == 0) red[threadIdx.x >> 5] = s;
    __syncthreads();
    if (threadIdx.x == 0) {
        float tot = 0.0f;
        int nw = blockDim.x >> 5;
        for (int w = 0; w < nw; w++) tot += red[w];
        float add;
        if (r < 2)      add = bl[r];
        else if (r < 4) add = br[r - 2];
        else            add = ob[r - 4];
        g_pre[r] = tot + add;
    }
}

// ---------------------------------------------------------------------------
// Kernel 2: binary-tree expansion.
// Thread t owns path bits s1..s17 (= bits 0..16 of t); it enumerates the
// 3 suffix bits s18..s20 and both j0 leaves, writing 16 rows of 32 floats.
// Warp lanes differ in the low bits (s1..s5) => each store step writes 32
// consecutive 128B rows (coalesced 4KB per warp per row-step).
// ---------------------------------------------------------------------------
__global__ void __launch_bounds__(128)
tree_kernel(const float* __restrict__ tl,   // (21,2,2)
            const float* __restrict__ tr,   // (21,2,2)
            const float* __restrict__ tbl,  // (21,2)
            const float* __restrict__ tbr,  // (21,2)
            const float* __restrict__ wout, // (21,32,2)
            float* __restrict__ out)
{
    __shared__ float s_wout[T_LEVELS * 64];  // [k][c][j]
    __shared__ float s_tree[T_LEVELS * 12];  // [k][branch]{m00,m01,m10,m11,b0,b1}
    __shared__ float s_pre[N_PRE];

    for (int i = threadIdx.x; i < T_LEVELS * 64; i += blockDim.x)
        s_wout[i] = wout[i];
    for (int i = threadIdx.x; i < T_LEVELS * 12; i += blockDim.x) {
        int k = i / 12, rem = i % 12, b = rem / 6, e = rem % 6;
        const float* M = b ? tr  : tl;
        const float* B = b ? tbr : tbl;
        s_tree[i] = (e < 4) ? M[k * 4 + e] : B[k * 2 + (e - 4)];
    }
    for (int i = threadIdx.x; i < N_PRE; i += blockDim.x)
        s_pre[i] = g_pre[i];
    __syncthreads();

    const unsigned t = blockIdx.x * blockDim.x + threadIdx.x; // 2^PREFIX_BITS threads

    // A = base accumulator; (va, vb) = v_k(a=0), v_k(a=1)
    float A[OUT_DIM];
    #pragma unroll
    for (int c = 0; c < OUT_DIM; c++) A[c] = s_pre[4 + c];
    float vax = s_pre[0], vay = s_pre[2];   // v0(0) = (left0[0], right0[0])
    float vbx = s_pre[1], vby = s_pre[3];   // v0(1) = (left0[1], right0[1])

    // ---- prefix walk: levels k = 0..PREFIX_BITS-1, bit b = s_{k+1} ----
    #pragma unroll 1
    for (int k = 0; k < PREFIX_BITS; k++) {
        unsigned b = (t >> k) & 1u;
        const float* W = s_wout + k * 64;
        float vsx = b ? vbx : vax;
        float vsy = b ? vby : vay;
        #pragma unroll
        for (int c = 0; c < OUT_DIM; c++)
            A[c] = fmaf(W[2 * c], vsx, fmaf(W[2 * c + 1], vsy, A[c]));
        const float* M = s_tree + k * 12 + b * 6;
        float m00 = M[0], m01 = M[1], m10 = M[2], m11 = M[3], c0 = M[4], c1 = M[5];
        float nax = fmaf(m00, vax, fmaf(m01, vay, c0));
        float nay = fmaf(m10, vax, fmaf(m11, vay, c1));
        float nbx = fmaf(m00, vbx, fmaf(m01, vby, c0));
        float nby = fmaf(m10, vbx, fmaf(m11, vby, c1));
        vax = nax; vay = nay; vbx = nbx; vby = nby;
    }

    // ---- suffix enumeration: bits s_{PREFIX+1}..s_20, then leaf j0 ----
    #pragma unroll 1
    for (unsigned u = 0; u < (1u << SUFFIX_BITS); ++u) {
        float Aw[OUT_DIM];
        #pragma unroll
        for (int c = 0; c < OUT_DIM; c++) Aw[c] = A[c];
        float wax = vax, way = vay, wbx = vbx, wby = vby;
        unsigned p = t;

        #pragma unroll
        for (int q = 0; q < SUFFIX_BITS; q++) {
            int k = PREFIX_BITS + q;
            unsigned b = (u >> q) & 1u;
            p |= b << k;
            const float* W = s_wout + k * 64;
            float vsx = b ? wbx : wax;
            float vsy = b ? wby : way;
            #pragma unroll
            for (int c = 0; c < OUT_DIM; c++)
                Aw[c] = fmaf(W[2 * c], vsx, fmaf(W[2 * c + 1], vsy, Aw[c]));
            const float* M = s_tree + k * 12 + b * 6;
            float m00 = M[0], m01 = M[1], m10 = M[2], m11 = M[3], c0 = M[4], c1 = M[5];
            float nax = fmaf(m00, wax, fmaf(m01, way, c0));
            float nay = fmaf(m10, wax, fmaf(m11, way, c1));
            float nbx = fmaf(m00, wbx, fmaf(m01, wby, c0));
            float nby = fmaf(m10, wbx, fmaf(m11, wby, c1));
            wax = nax; way = nay; wbx = nbx; wby = nby;
        }

        // leaves: level 20, j0 selects (wa | wb); j0 is output bit 20
        const float* W = s_wout + 20 * 64;
        float4* o0 = reinterpret_cast<float4*>(out + (size_t)p * OUT_DIM);
        float4* o1 = reinterpret_cast<float4*>(out + ((size_t)p + (1u << 20)) * OUT_DIM);
        #pragma unroll
        for (int c4 = 0; c4 < 8; c4++) {
            int c = c4 * 4;
            float4 r0, r1;
            float w0_ = W[2 * (c + 0)], w1_ = W[2 * (c + 0) + 1];
            r0.x = fmaf(w0_, wax, fmaf(w1_, way, Aw[c + 0]));
            r1.x = fmaf(w0_, wbx, fmaf(w1_, wby, Aw[c + 0]));
            w0_ = W[2 * (c + 1)]; w1_ = W[2 * (c + 1) + 1];
            r0.y = fmaf(w0_, wax, fmaf(w1_, way, Aw[c + 1]));
            r1.y = fmaf(w0_, wbx, fmaf(w1_, wby, Aw[c + 1]));
            w0_ = W[2 * (c + 2)]; w1_ = W[2 * (c + 2) + 1];
            r0.z = fmaf(w0_, wax, fmaf(w1_, way, Aw[c + 2]));
            r1.z = fmaf(w0_, wbx, fmaf(w1_, wby, Aw[c + 2]));
            w0_ = W[2 * (c + 3)]; w1_ = W[2 * (c + 3) + 1];
            r0.w = fmaf(w0_, wax, fmaf(w1_, way, Aw[c + 3]));
            r1.w = fmaf(w0_, wbx, fmaf(w1_, wby, Aw[c + 3]));
            o0[c4] = r0;
            o1[c4] = r1;
        }
    }
}

// ---------------------------------------------------------------------------
extern "C" void kernel_launch(void* const* d_in, const int* in_sizes, int n_in,
                              void* d_out, int out_size)
{
    const float* x    = (const float*)d_in[0];
    const float* wl   = (const float*)d_in[1];
    const float* wr   = (const float*)d_in[2];
    const float* bl   = (const float*)d_in[3];
    const float* br   = (const float*)d_in[4];
    const float* tl   = (const float*)d_in[5];
    const float* tr   = (const float*)d_in[6];
    const float* tbl  = (const float*)d_in[7];
    const float* tbr  = (const float*)d_in[8];
    const float* w0   = (const float*)d_in[9];
    const float* wout = (const float*)d_in[10];
    const float* ob   = (const float*)d_in[11];

    precompute_kernel<<<N_PRE, 256>>>(x, wl, wr, bl, br, w0, ob);

    const int threads = 1 << PREFIX_BITS;
    tree_kernel<<<threads / 128, 128>>>(tl, tr, tbl, tbr, wout, (float*)d_out);
}